// round 16
// baseline (speedup 1.0000x reference)
#include <cuda_runtime.h>
#include <cuda_fp16.h>
#include <cstdint>

#define HEADS 6
#define DIM 192
#define NTOK 49
#define THREADS 384
#define ST 200                 // fp16 row stride (400B)
#define WOFF 56                // window B row offset (M packed: A 0-48, B 56-104)

// smem byte offsets
#define SM_XHI   0             // [112][200] x / AV-out
#define SM_QHI   44800         // [120][200] Q (pre-scaled)
#define SM_KHI   92800         // [120][200] K
#define SM_VHI   140800        // [120][200] V
#define SM_TOTAL 188800

// ---- helpers ----
__device__ __forceinline__ uint32_t smem_u32(const void* p) {
    uint32_t a;
    asm("{ .reg .u64 t; cvta.to.shared.u64 t, %1; cvt.u32.u64 %0, t; }" : "=r"(a) : "l"(p));
    return a;
}
__device__ __forceinline__ void ldm4(uint32_t* r, uint32_t addr) {
    asm volatile("ldmatrix.sync.aligned.m8n8.x4.shared.b16 {%0,%1,%2,%3}, [%4];"
        : "=r"(r[0]), "=r"(r[1]), "=r"(r[2]), "=r"(r[3]) : "r"(addr));
}
__device__ __forceinline__ void ldm2(uint32_t* r, uint32_t addr) {
    asm volatile("ldmatrix.sync.aligned.m8n8.x2.shared.b16 {%0,%1}, [%2];"
        : "=r"(r[0]), "=r"(r[1]) : "r"(addr));
}
__device__ __forceinline__ void ldm4t(uint32_t* r, uint32_t addr) {
    asm volatile("ldmatrix.sync.aligned.m8n8.x4.trans.shared.b16 {%0,%1,%2,%3}, [%4];"
        : "=r"(r[0]), "=r"(r[1]), "=r"(r[2]), "=r"(r[3]) : "r"(addr));
}
__device__ __forceinline__ void mma16816(float* c, const uint32_t* a, uint2 b) {
    asm volatile("mma.sync.aligned.m16n8k16.row.col.f32.f16.f16.f32 "
        "{%0,%1,%2,%3},{%4,%5,%6,%7},{%8,%9},{%0,%1,%2,%3};"
        : "+f"(c[0]), "+f"(c[1]), "+f"(c[2]), "+f"(c[3])
        : "r"(a[0]), "r"(a[1]), "r"(a[2]), "r"(a[3]), "r"(b.x), "r"(b.y));
}
__device__ __forceinline__ uint32_t hpack(float a, float b) {
    __half2 h = __floats2half2_rn(a, b);
    return *(uint32_t*)&h;
}
__device__ __forceinline__ bool row_valid(int r) {
    return (r < NTOK) || ((unsigned)(r - WOFF) < (unsigned)NTOK);
}

// ---- pre-packed weight B fragments (fp16, single term) ----
#define NQF (72 * 12 * 32)
#define NPF (24 * 12 * 32)
__device__ uint2 g_bqkv[NQF];
__device__ uint2 g_bproj[NPF];
// combined bias+mask, fp16x2 pairs: [64][6][49][28]
#define CM_N (64 * 6 * 49 * 28)
__device__ uint32_t g_cmask[CM_N];

__global__ void prep_frags(const float* __restrict__ qkv_w,
                           const float* __restrict__ proj_w)
{
    int idx = blockIdx.x * blockDim.x + threadIdx.x;
    if (idx >= NQF + NPF) return;
    const float* W; uint2* dst; int e;
    if (idx < NQF) { e = idx; W = qkv_w; dst = g_bqkv + idx; }
    else { e = idx - NQF; W = proj_w; dst = g_bproj + e; }
    int lane = e & 31, ks = (e >> 5) % 12, nt = (e >> 5) / 12;
    int j = nt * 8 + (lane >> 2);
    int k = ks * 16 + (lane & 3) * 2;
    const float* wr = W + (size_t)j * DIM;
    uint2 v;
    v.x = hpack(wr[k],     wr[k + 1]);
    v.y = hpack(wr[k + 8], wr[k + 9]);
    *dst = v;
}

__global__ void prep_cmask(const int* __restrict__ rpi_raw,
                           const float* __restrict__ mask,
                           const float* __restrict__ rpb)
{
    int idx = blockIdx.x * blockDim.x + threadIdx.x;
    if (idx >= CM_N) return;
    int jp = idx % 28;
    int i  = (idx / 28) % 49;
    int h  = (idx / (28 * 49)) % 6;
    int w  = idx / (28 * 49 * 6);
    bool is64 = (rpi_raw[1] == 0) && (rpi_raw[3] == 0) && (rpi_raw[5] == 0)
             && (rpi_raw[7] == 0) && (rpi_raw[9] == 0);
    float v[2];
    #pragma unroll
    for (int t = 0; t < 2; t++) {
        int j = jp * 2 + t;
        if (j < 49) {
            int e = i * 49 + j;
            int r = is64 ? rpi_raw[2 * e] : rpi_raw[e];
            v[t] = rpb[r * 6 + h] + mask[w * 2401 + e];
        } else v[t] = -30000.f;
    }
    g_cmask[idx] = hpack(v[0], v[1]);
}

// ---- GEMM chunk: 7 m-tiles x NT n-tiles x 12 k-steps, single-term fp16 ----
template <int NT>
__device__ __forceinline__ void gemm_chunk7(uint32_t aHi,
                                            const uint2* __restrict__ bhi,
                                            float acc[NT][7][4])
{
    #pragma unroll
    for (int n = 0; n < NT; n++)
        #pragma unroll
        for (int m = 0; m < 7; m++)
            #pragma unroll
            for (int q = 0; q < 4; q++) acc[n][m][q] = 0.f;
    #pragma unroll
    for (int ks = 0; ks < 12; ks++) {
        uint2 bh[NT];
        #pragma unroll
        for (int n = 0; n < NT; n++) bh[n] = bhi[(n * 12 + ks) * 32];
        #pragma unroll
        for (int m = 0; m < 7; m++) {
            uint32_t ah[4];
            ldm4(ah, aHi + m * 6400 + ks * 32);
            #pragma unroll
            for (int n = 0; n < NT; n++)
                mma16816(acc[n][m], ah, bh[n]);
        }
    }
}

extern "C" __global__ void __launch_bounds__(THREADS, 1)
win_attn_kernel(const float* __restrict__ x,
                const float* __restrict__ qkv_b,
                const float* __restrict__ proj_b,
                float* __restrict__ out)
{
    extern __shared__ char smem[];
    __half* xhi = (__half*)(smem + SM_XHI);
    __half* qhi = (__half*)(smem + SM_QHI);
    __half* khi = (__half*)(smem + SM_KHI);
    __half* vhi = (__half*)(smem + SM_VHI);

    const int tid  = threadIdx.x;
    const int bw0  = blockIdx.x * 2;
    const int lane = tid & 31, warp = tid >> 5;
    const int gid = lane >> 2, tig = lane & 3;
    const uint32_t sb = smem_u32(smem);

    // ldmatrix A-operand lane addressing (validated R7-R15)
    const int rowA = (lane & 7) + ((lane >> 3) & 1) * 8;
    const int colA = (lane >> 4) * 8;
    const uint32_t aHi = sb + SM_XHI + (uint32_t)(rowA * ST + colA) * 2;

    // ---------------- Phase 1: stage 2 windows' x -> fp16; zero pads ----------------
    {
        for (int idx = tid; idx < 112 * 6; idx += THREADS) {
            int r  = idx / 6, cg = idx - r * 6;
            int w  = (r >= WOFF) ? 1 : 0;
            int lr = r - w * WOFF;
            bool real = lr < NTOK;
            const float* xr = x + ((size_t)(bw0 + w) * NTOK + lr) * DIM + cg * 32;
            uint32_t* dh = (uint32_t*)(xhi + r * ST + cg * 32);
            #pragma unroll
            for (int c = 0; c < 32; c += 2) {
                float2 v = real ? *(const float2*)(xr + c) : make_float2(0.f, 0.f);
                dh[c >> 1] = hpack(v.x, v.y);
            }
        }
        // zero pad rows 49-55 and 105-119 of Q, K, V
        for (int i = tid; i < 3 * 22 * 100; i += THREADS) {
            int buf = i / 2200;
            int rem = i - buf * 2200;
            int ri = rem / 100, cc = rem - ri * 100;
            int rr = (ri < 7) ? 49 + ri : 105 + (ri - 7);
            uint32_t* b32 = (uint32_t*)((buf == 0) ? qhi : (buf == 1) ? khi : vhi);
            b32[rr * 100 + cc] = 0;
        }
    }
    __syncthreads();

    // ---------------- Phase 2: QKV GEMM (1-term), M=112, 72 n-tiles / 12 warps ----------------
    {
        const float scale = 0.17677669529663687f;
        const int g = warp >> 2;   // 0=Q 1=K 2=V
        __half* dh = (g == 0) ? qhi : (g == 1) ? khi : vhi;
        const float smul = (g == 0) ? scale : 1.f;
        #pragma unroll 1
        for (int c = 0; c < 3; c++) {
            const int ntbase = warp * 6 + c * 2;
            const uint2* bhi = g_bqkv + (size_t)ntbase * 384 + lane;
            float acc[2][7][4];
            gemm_chunk7<2>(aHi, bhi, acc);
            #pragma unroll
            for (int n = 0; n < 2; n++) {
                int col = (ntbase + n) * 8 + tig * 2;
                int cc = col - g * 192;
                float b0 = qkv_b[col], b1 = qkv_b[col + 1];
                #pragma unroll
                for (int m = 0; m < 7; m++) {
                    int r0 = m * 16 + gid;
                    int r1 = r0 + 8;
                    if (row_valid(r0))
                        *(uint32_t*)(dh + r0 * ST + cc) =
                            hpack(smul * (acc[n][m][0] + b0), smul * (acc[n][m][1] + b1));
                    if (row_valid(r1))
                        *(uint32_t*)(dh + r1 * ST + cc) =
                            hpack(smul * (acc[n][m][2] + b0), smul * (acc[n][m][3] + b1));
                }
            }
        }
    }
    __syncthreads();

    // ---------------- Phase 3: attention (warp = head x row-half; loop 2 windows) ----------------
    {
        const int h  = warp >> 1;
        const int mh = warp & 1;
        const int qo = h * 32;
        const int kq  = lane & 7;
        const int kb3 = (lane >> 3) & 1;
        const int kb4 = lane >> 4;

        #pragma unroll 1
        for (int iw = 0; iw < 2; iw++) {
            const int wo = iw * WOFF;
            const int widx = (bw0 + iw) & 63;
            const uint32_t* cm = g_cmask + ((size_t)(widx * 6 + h) * 49) * 28;

            const uint32_t aQh = sb + SM_QHI
                + (uint32_t)((wo + mh * 32 + rowA) * ST + qo + colA) * 2;
            // K x4: n-tile pairs. lanes: row = kq + kb4*8, col-half = kb3
            const uint32_t bK4 = sb + SM_KHI
                + (uint32_t)((wo + kq + kb4 * 8) * ST + qo + kb3 * 8) * 2;
            // K x2 leftover (n=6): lanes 0-15 meaningful
            const uint32_t bK2 = sb + SM_KHI
                + (uint32_t)((wo + kq) * ST + qo + kb3 * 8) * 2;
            // V x4 trans: nd pairs. lanes: token row = kq + kb3*8, col += kb4*8
            const uint32_t bV4 = sb + SM_VHI
                + (uint32_t)((wo + kq + kb3 * 8) * ST + qo) * 2 + (uint32_t)kb4 * 16;

            // ---- hoisted V fragments (identical across both m-tiles) ----
            uint32_t vf[32];
            #pragma unroll
            for (int jt = 0; jt < 4; jt++)
                #pragma unroll
                for (int p = 0; p < 2; p++)
                    ldm4t(vf + jt * 8 + p * 4, bV4 + jt * 6400 + p * 32);

            #pragma unroll 1
            for (int m = 0; m < 2; m++) {
                const int i0 = mh * 32 + m * 16 + gid;   // local query row
                const int i1 = i0 + 8;

                // ---- prefetch bias+mask (overlaps LDG latency with mma below) ----
                uint32_t cp0[7], cp1[7];
                #pragma unroll
                for (int n = 0; n < 7; n++) {
                    cp0[n] = (i0 < NTOK) ? cm[i0 * 28 + n * 4 + tig] : 0;
                    cp1[n] = (i1 < NTOK) ? cm[i1 * 28 + n * 4 + tig] : 0;
                }

                // ---- scores: S = Q K^T (1-term; Q pre-scaled), K via x4 pairs ----
                float sc[7][4];
                #pragma unroll
                for (int n = 0; n < 7; n++)
                    #pragma unroll
                    for (int q = 0; q < 4; q++) sc[n][q] = 0.f;
                #pragma unroll
                for (int ks = 0; ks < 2; ks++) {
                    uint32_t ah[4];
                    ldm4(ah, aQh + m * 6400 + ks * 32);
                    #pragma unroll
                    for (int np = 0; np < 3; np++) {
                        uint32_t kk[4];
                        ldm4(kk, bK4 + np * 6400 + ks * 32);
                        mma16816(sc[2 * np],     ah, make_uint2(kk[0], kk[1]));
                        mma16816(sc[2 * np + 1], ah, make_uint2(kk[2], kk[3]));
                    }
                    uint32_t k2[2];
                    ldm2(k2, bK2 + 6 * 3200 + ks * 32);
                    mma16816(sc[6], ah, make_uint2(k2[0], k2[1]));
                }

                // ---- + bias+mask ----
                #pragma unroll
                for (int n = 0; n < 7; n++) {
                    if (i0 < NTOK) {
                        __half2 cf = *(__half2*)&cp0[n];
                        sc[n][0] += __half2float(cf.x);
                        sc[n][1] += __half2float(cf.y);
                    } else { sc[n][0] = -30000.f; sc[n][1] = -30000.f; }
                    if (i1 < NTOK) {
                        __half2 cf = *(__half2*)&cp1[n];
                        sc[n][2] += __half2float(cf.x);
                        sc[n][3] += __half2float(cf.y);
                    } else { sc[n][2] = -30000.f; sc[n][3] = -30000.f; }
                }

                // ---- row softmax: exp only; normalization deferred to fp32 epilogue ----
                float mA = -1e30f, mB = -1e30f;
                #pragma unroll
                for (int n = 0; n < 7; n++) {
                    mA = fmaxf(mA, fmaxf(sc[n][0], sc[n][1]));
                    mB = fmaxf(mB, fmaxf(sc[n][2], sc[n][3]));
                }
                mA = fmaxf(mA, __shfl_xor_sync(0xffffffffu, mA, 1));
                mA = fmaxf(mA, __shfl_xor_sync(0xffffffffu, mA, 2));
                mB = fmaxf(mB, __shfl_xor_sync(0xffffffffu, mB, 1));
                mB = fmaxf(mB, __shfl_xor_sync(0xffffffffu, mB, 2));
                float sA = 0.f, sB = 0.f;
                #pragma unroll
                for (int n = 0; n < 7; n++) {
                    sc[n][0] = __expf(sc[n][0] - mA); sA += sc[n][0];
                    sc[n][1] = __expf(sc[n][1] - mA); sA += sc[n][1];
                    sc[n][2] = __expf(sc[n][2] - mB); sB += sc[n][2];
                    sc[n][3] = __expf(sc[n][3] - mB); sB += sc[n][3];
                }
                sA += __shfl_xor_sync(0xffffffffu, sA, 1);
                sA += __shfl_xor_sync(0xffffffffu, sA, 2);
                sB += __shfl_xor_sync(0xffffffffu, sB, 1);
                sB += __shfl_xor_sync(0xffffffffu, sB, 2);
                float rA = 1.f / sA, rB = 1.f / sB;

                // ---- AV: out = P V (1-term, P = unnormalized exp), V from hoisted frags ----
                float av[4][4];
                #pragma unroll
                for (int nd = 0; nd < 4; nd++)
                    #pragma unroll
                    for (int q = 0; q < 4; q++) av[nd][q] = 0.f;
                #pragma unroll
                for (int jt = 0; jt < 4; jt++) {
                    int nA = 2 * jt, nB = 2 * jt + 1;
                    uint32_t ph[4];
                    ph[0] = hpack(sc[nA][0], sc[nA][1]);
                    ph[1] = hpack(sc[nA][2], sc[nA][3]);
                    if (nB < 7) {
                        ph[2] = hpack(sc[nB][0], sc[nB][1]);
                        ph[3] = hpack(sc[nB][2], sc[nB][3]);
                    } else { ph[2] = 0; ph[3] = 0; }
                    #pragma unroll
                    for (int nd = 0; nd < 4; nd++) {
                        int p = nd >> 1, q = nd & 1;
                        uint2 BH = make_uint2(vf[jt * 8 + p * 4 + 2 * q],
                                              vf[jt * 8 + p * 4 + 2 * q + 1]);
                        mma16816(av[nd], ph, BH);
                    }
                }

                // ---- normalize in fp32, store AV out (single fp16) as proj A input ----
                #pragma unroll
                for (int nd = 0; nd < 4; nd++) {
                    int col = qo + nd * 8 + tig * 2;
                    if (i0 < NTOK)
                        *(uint32_t*)(xhi + (wo + i0) * ST + col) =
                            hpack(av[nd][0] * rA, av[nd][1] * rA);
                    if (i1 < NTOK)
                        *(uint32_t*)(xhi + (wo + i1) * ST + col) =
                            hpack(av[nd][2] * rB, av[nd][3] * rB);
                }
            }
        }
    }
    __syncthreads();

    // ---------------- Phase 4: proj GEMM (1-term), M=112, 24 n-tiles / 12 warps ----------------
    {
        const int ntbase = warp * 2;
        const uint2* bhi = g_bproj + (size_t)ntbase * 384 + lane;
        float acc[2][7][4];
        gemm_chunk7<2>(aHi, bhi, acc);
        #pragma unroll
        for (int n = 0; n < 2; n++) {
            int col = (ntbase + n) * 8 + tig * 2;
            float b0 = proj_b[col], b1 = proj_b[col + 1];
            #pragma unroll
            for (int m = 0; m < 7; m++) {
                int r0 = m * 16 + gid;
                int r1 = r0 + 8;
                if (row_valid(r0)) {
                    int w = (r0 >= WOFF) ? 1 : 0;
                    float* og = out + ((size_t)(bw0 + w) * NTOK + (r0 - w * WOFF)) * DIM;
                    *(float2*)(og + col) = make_float2(acc[n][m][0] + b0, acc[n][m][1] + b1);
                }
                if (row_valid(r1)) {
                    int w = (r1 >= WOFF) ? 1 : 0;
                    float* og = out + ((size_t)(bw0 + w) * NTOK + (r1 - w * WOFF)) * DIM;
                    *(float2*)(og + col) = make_float2(acc[n][m][2] + b0, acc[n][m][3] + b1);
                }
            }
        }
    }
}

extern "C" void kernel_launch(void* const* d_in, const int* in_sizes, int n_in,
                              void* d_out, int out_size)
{
    const float* x      = (const float*)d_in[0];
    const int*   rpi    = (const int*)d_in[1];
    const float* mask   = (const float*)d_in[2];
    const float* qkv_w  = (const float*)d_in[3];
    const float* qkv_b  = (const float*)d_in[4];
    const float* proj_w = (const float*)d_in[5];
    const float* proj_b = (const float*)d_in[6];
    const float* rpb    = (const float*)d_in[7];

    prep_frags<<<(NQF + NPF + 255) / 256, 256>>>(qkv_w, proj_w);
    prep_cmask<<<(CM_N + 255) / 256, 256>>>(rpi, mask, rpb);

    cudaFuncSetAttribute(win_attn_kernel,
                         cudaFuncAttributeMaxDynamicSharedMemorySize, SM_TOTAL);
    win_attn_kernel<<<2048, THREADS, SM_TOTAL>>>(x, qkv_b, proj_b, (float*)d_out);
}

// round 17
// speedup vs baseline: 1.0176x; 1.0176x over previous
#include <cuda_runtime.h>
#include <cuda_fp16.h>
#include <cstdint>

#define HEADS 6
#define DIM 192
#define NTOK 49
#define THREADS 384
#define ST 200                 // fp16 row stride (400B)
#define WOFF 56                // window B row offset (M packed: A 0-48, B 56-104)

// smem byte offsets
#define SM_XHI   0             // [112][200] x / AV-out
#define SM_QHI   44800         // [120][200] Q (pre-scaled)
#define SM_KHI   92800         // [120][200] K
#define SM_VHI   140800        // [120][200] V
#define SM_TOTAL 188800

// ---- helpers ----
__device__ __forceinline__ uint32_t smem_u32(const void* p) {
    uint32_t a;
    asm("{ .reg .u64 t; cvta.to.shared.u64 t, %1; cvt.u32.u64 %0, t; }" : "=r"(a) : "l"(p));
    return a;
}
__device__ __forceinline__ void ldm4(uint32_t* r, uint32_t addr) {
    asm volatile("ldmatrix.sync.aligned.m8n8.x4.shared.b16 {%0,%1,%2,%3}, [%4];"
        : "=r"(r[0]), "=r"(r[1]), "=r"(r[2]), "=r"(r[3]) : "r"(addr));
}
__device__ __forceinline__ void ldm2(uint32_t* r, uint32_t addr) {
    asm volatile("ldmatrix.sync.aligned.m8n8.x2.shared.b16 {%0,%1}, [%2];"
        : "=r"(r[0]), "=r"(r[1]) : "r"(addr));
}
__device__ __forceinline__ void ldm4t(uint32_t* r, uint32_t addr) {
    asm volatile("ldmatrix.sync.aligned.m8n8.x4.trans.shared.b16 {%0,%1,%2,%3}, [%4];"
        : "=r"(r[0]), "=r"(r[1]), "=r"(r[2]), "=r"(r[3]) : "r"(addr));
}
__device__ __forceinline__ void mma16816(float* c, const uint32_t* a, uint2 b) {
    asm volatile("mma.sync.aligned.m16n8k16.row.col.f32.f16.f16.f32 "
        "{%0,%1,%2,%3},{%4,%5,%6,%7},{%8,%9},{%0,%1,%2,%3};"
        : "+f"(c[0]), "+f"(c[1]), "+f"(c[2]), "+f"(c[3])
        : "r"(a[0]), "r"(a[1]), "r"(a[2]), "r"(a[3]), "r"(b.x), "r"(b.y));
}
__device__ __forceinline__ uint32_t hpack(float a, float b) {
    __half2 h = __floats2half2_rn(a, b);
    return *(uint32_t*)&h;
}
__device__ __forceinline__ bool row_valid(int r) {
    return (r < NTOK) || ((unsigned)(r - WOFF) < (unsigned)NTOK);
}

// ---- pre-packed weight B fragments (fp16, single term) ----
#define NQF (72 * 12 * 32)
#define NPF (24 * 12 * 32)
__device__ uint2 g_bqkv[NQF];
__device__ uint2 g_bproj[NPF];
// combined bias+mask, fp16x2 pairs: [64][6][49][28]
#define CM_N (64 * 6 * 49 * 28)
__device__ uint32_t g_cmask[CM_N];

// ---- fused prep: weight fragments + combined bias/mask table ----
__global__ void prep_all(const float* __restrict__ qkv_w,
                         const float* __restrict__ proj_w,
                         const int* __restrict__ rpi_raw,
                         const float* __restrict__ mask,
                         const float* __restrict__ rpb)
{
    int idx = blockIdx.x * blockDim.x + threadIdx.x;
    if (idx < NQF + NPF) {
        const float* W; uint2* dst; int e;
        if (idx < NQF) { e = idx; W = qkv_w; dst = g_bqkv + idx; }
        else { e = idx - NQF; W = proj_w; dst = g_bproj + e; }
        int lane = e & 31, ks = (e >> 5) % 12, nt = (e >> 5) / 12;
        int j = nt * 8 + (lane >> 2);
        int k = ks * 16 + (lane & 3) * 2;
        const float* wr = W + (size_t)j * DIM;
        uint2 v;
        v.x = hpack(wr[k],     wr[k + 1]);
        v.y = hpack(wr[k + 8], wr[k + 9]);
        *dst = v;
        return;
    }
    int cidx = idx - (NQF + NPF);
    if (cidx >= CM_N) return;
    int jp = cidx % 28;
    int i  = (cidx / 28) % 49;
    int h  = (cidx / (28 * 49)) % 6;
    int w  = cidx / (28 * 49 * 6);
    bool is64 = (rpi_raw[1] == 0) && (rpi_raw[3] == 0) && (rpi_raw[5] == 0)
             && (rpi_raw[7] == 0) && (rpi_raw[9] == 0);
    float v[2];
    #pragma unroll
    for (int t = 0; t < 2; t++) {
        int j = jp * 2 + t;
        if (j < 49) {
            int e = i * 49 + j;
            int r = is64 ? rpi_raw[2 * e] : rpi_raw[e];
            v[t] = rpb[r * 6 + h] + mask[w * 2401 + e];
        } else v[t] = -30000.f;
    }
    g_cmask[cidx] = hpack(v[0], v[1]);
}

// load NT*12 B-fragments (uint2 each) into registers
template <int NT>
__device__ __forceinline__ void load_frags(const uint2* __restrict__ bhi, uint2* pre)
{
    #pragma unroll
    for (int i = 0; i < NT * 12; i++) pre[i] = bhi[i * 32];
}

// GEMM chunk with PRELOADED B fragments: 7 m-tiles x NT n-tiles x 12 k-steps
template <int NT>
__device__ __forceinline__ void gemm_chunk7_pre(uint32_t aHi, const uint2* pre,
                                                float acc[NT][7][4])
{
    #pragma unroll
    for (int n = 0; n < NT; n++)
        #pragma unroll
        for (int m = 0; m < 7; m++)
            #pragma unroll
            for (int q = 0; q < 4; q++) acc[n][m][q] = 0.f;
    #pragma unroll
    for (int ks = 0; ks < 12; ks++) {
        #pragma unroll
        for (int m = 0; m < 7; m++) {
            uint32_t ah[4];
            ldm4(ah, aHi + m * 6400 + ks * 32);
            #pragma unroll
            for (int n = 0; n < NT; n++)
                mma16816(acc[n][m], ah, pre[n * 12 + ks]);
        }
    }
}

extern "C" __global__ void __launch_bounds__(THREADS, 1)
win_attn_kernel(const float* __restrict__ x,
                const float* __restrict__ qkv_b,
                const float* __restrict__ proj_b,
                float* __restrict__ out)
{
    extern __shared__ char smem[];
    __half* xhi = (__half*)(smem + SM_XHI);
    __half* qhi = (__half*)(smem + SM_QHI);
    __half* khi = (__half*)(smem + SM_KHI);
    __half* vhi = (__half*)(smem + SM_VHI);

    const int tid  = threadIdx.x;
    const int bw0  = blockIdx.x * 2;
    const int lane = tid & 31, warp = tid >> 5;
    const int gid = lane >> 2, tig = lane & 3;
    const uint32_t sb = smem_u32(smem);

    // ldmatrix A-operand lane addressing (validated R7-R16)
    const int rowA = (lane & 7) + ((lane >> 3) & 1) * 8;
    const int colA = (lane >> 4) * 8;
    const uint32_t aHi = sb + SM_XHI + (uint32_t)(rowA * ST + colA) * 2;

    // ---------------- Phase 1: stage 2 windows' x -> fp16; zero pads ----------------
    {
        for (int idx = tid; idx < 112 * 6; idx += THREADS) {
            int r  = idx / 6, cg = idx - r * 6;
            int w  = (r >= WOFF) ? 1 : 0;
            int lr = r - w * WOFF;
            bool real = lr < NTOK;
            const float* xr = x + ((size_t)(bw0 + w) * NTOK + lr) * DIM + cg * 32;
            uint32_t* dh = (uint32_t*)(xhi + r * ST + cg * 32);
            #pragma unroll
            for (int c = 0; c < 32; c += 2) {
                float2 v = real ? *(const float2*)(xr + c) : make_float2(0.f, 0.f);
                dh[c >> 1] = hpack(v.x, v.y);
            }
        }
        // zero pad rows 49-55 and 105-119 of Q, K, V
        for (int i = tid; i < 3 * 22 * 100; i += THREADS) {
            int buf = i / 2200;
            int rem = i - buf * 2200;
            int ri = rem / 100, cc = rem - ri * 100;
            int rr = (ri < 7) ? 49 + ri : 105 + (ri - 7);
            uint32_t* b32 = (uint32_t*)((buf == 0) ? qhi : (buf == 1) ? khi : vhi);
            b32[rr * 100 + cc] = 0;
        }
    }

    // preload qkv chunk-0 fragments BEFORE the barrier (LDG overlaps barrier drain)
    uint2 pre[24];
    load_frags<2>(g_bqkv + (size_t)(warp * 6) * 384 + lane, pre);
    __syncthreads();

    // ---------------- Phase 2: QKV GEMM (1-term), pipelined frag loads ----------------
    {
        const float scale = 0.17677669529663687f;
        const int g = warp >> 2;   // 0=Q 1=K 2=V
        __half* dh = (g == 0) ? qhi : (g == 1) ? khi : vhi;
        const float smul = (g == 0) ? scale : 1.f;
        #pragma unroll 1
        for (int c = 0; c < 3; c++) {
            const int ntbase = warp * 6 + c * 2;
            float acc[2][7][4];
            gemm_chunk7_pre<2>(aHi, pre, acc);
            // issue next chunk's LDGs now; epilogue below hides their latency
            if (c < 2)
                load_frags<2>(g_bqkv + (size_t)(ntbase + 2) * 384 + lane, pre);
            #pragma unroll
            for (int n = 0; n < 2; n++) {
                int col = (ntbase + n) * 8 + tig * 2;
                int cc = col - g * 192;
                float b0 = qkv_b[col], b1 = qkv_b[col + 1];
                #pragma unroll
                for (int m = 0; m < 7; m++) {
                    int r0 = m * 16 + gid;
                    int r1 = r0 + 8;
                    if (row_valid(r0))
                        *(uint32_t*)(dh + r0 * ST + cc) =
                            hpack(smul * (acc[n][m][0] + b0), smul * (acc[n][m][1] + b1));
                    if (row_valid(r1))
                        *(uint32_t*)(dh + r1 * ST + cc) =
                            hpack(smul * (acc[n][m][2] + b0), smul * (acc[n][m][3] + b1));
                }
            }
        }
    }
    __syncthreads();

    // ---------------- Phase 3: attention (warp = head x row-half; loop 2 windows) ----------------
    {
        const int h  = warp >> 1;
        const int mh = warp & 1;
        const int qo = h * 32;
        const int kq  = lane & 7;
        const int kb3 = (lane >> 3) & 1;
        const int kb4 = lane >> 4;

        #pragma unroll 1
        for (int iw = 0; iw < 2; iw++) {
            const int wo = iw * WOFF;
            const int widx = (bw0 + iw) & 63;
            const uint32_t* cm = g_cmask + ((size_t)(widx * 6 + h) * 49) * 28;

            const uint32_t aQh = sb + SM_QHI
                + (uint32_t)((wo + mh * 32 + rowA) * ST + qo + colA) * 2;
            const uint32_t bK4 = sb + SM_KHI
                + (uint32_t)((wo + kq + kb4 * 8) * ST + qo + kb3 * 8) * 2;
            const uint32_t bK2 = sb + SM_KHI
                + (uint32_t)((wo + kq) * ST + qo + kb3 * 8) * 2;
            const uint32_t bV4 = sb + SM_VHI
                + (uint32_t)((wo + kq + kb3 * 8) * ST + qo) * 2 + (uint32_t)kb4 * 16;

            // hoisted V fragments (identical across both m-tiles)
            uint32_t vf[32];
            #pragma unroll
            for (int jt = 0; jt < 4; jt++)
                #pragma unroll
                for (int p = 0; p < 2; p++)
                    ldm4t(vf + jt * 8 + p * 4, bV4 + jt * 6400 + p * 32);

            #pragma unroll 1
            for (int m = 0; m < 2; m++) {
                const int i0 = mh * 32 + m * 16 + gid;
                const int i1 = i0 + 8;

                // prefetch bias+mask
                uint32_t cp0[7], cp1[7];
                #pragma unroll
                for (int n = 0; n < 7; n++) {
                    cp0[n] = (i0 < NTOK) ? cm[i0 * 28 + n * 4 + tig] : 0;
                    cp1[n] = (i1 < NTOK) ? cm[i1 * 28 + n * 4 + tig] : 0;
                }

                // scores: S = Q K^T (1-term; Q pre-scaled), K via x4 pairs
                float sc[7][4];
                #pragma unroll
                for (int n = 0; n < 7; n++)
                    #pragma unroll
                    for (int q = 0; q < 4; q++) sc[n][q] = 0.f;
                #pragma unroll
                for (int ks = 0; ks < 2; ks++) {
                    uint32_t ah[4];
                    ldm4(ah, aQh + m * 6400 + ks * 32);
                    #pragma unroll
                    for (int np = 0; np < 3; np++) {
                        uint32_t kk[4];
                        ldm4(kk, bK4 + np * 6400 + ks * 32);
                        mma16816(sc[2 * np],     ah, make_uint2(kk[0], kk[1]));
                        mma16816(sc[2 * np + 1], ah, make_uint2(kk[2], kk[3]));
                    }
                    uint32_t k2[2];
                    ldm2(k2, bK2 + 6 * 3200 + ks * 32);
                    mma16816(sc[6], ah, make_uint2(k2[0], k2[1]));
                }

                // + bias+mask
                #pragma unroll
                for (int n = 0; n < 7; n++) {
                    if (i0 < NTOK) {
                        __half2 cf = *(__half2*)&cp0[n];
                        sc[n][0] += __half2float(cf.x);
                        sc[n][1] += __half2float(cf.y);
                    } else { sc[n][0] = -30000.f; sc[n][1] = -30000.f; }
                    if (i1 < NTOK) {
                        __half2 cf = *(__half2*)&cp1[n];
                        sc[n][2] += __half2float(cf.x);
                        sc[n][3] += __half2float(cf.y);
                    } else { sc[n][2] = -30000.f; sc[n][3] = -30000.f; }
                }

                // row softmax: exp only; normalization deferred
                float mA = -1e30f, mB = -1e30f;
                #pragma unroll
                for (int n = 0; n < 7; n++) {
                    mA = fmaxf(mA, fmaxf(sc[n][0], sc[n][1]));
                    mB = fmaxf(mB, fmaxf(sc[n][2], sc[n][3]));
                }
                mA = fmaxf(mA, __shfl_xor_sync(0xffffffffu, mA, 1));
                mA = fmaxf(mA, __shfl_xor_sync(0xffffffffu, mA, 2));
                mB = fmaxf(mB, __shfl_xor_sync(0xffffffffu, mB, 1));
                mB = fmaxf(mB, __shfl_xor_sync(0xffffffffu, mB, 2));
                float sA = 0.f, sB = 0.f;
                #pragma unroll
                for (int n = 0; n < 7; n++) {
                    sc[n][0] = __expf(sc[n][0] - mA); sA += sc[n][0];
                    sc[n][1] = __expf(sc[n][1] - mA); sA += sc[n][1];
                    sc[n][2] = __expf(sc[n][2] - mB); sB += sc[n][2];
                    sc[n][3] = __expf(sc[n][3] - mB); sB += sc[n][3];
                }
                sA += __shfl_xor_sync(0xffffffffu, sA, 1);
                sA += __shfl_xor_sync(0xffffffffu, sA, 2);
                sB += __shfl_xor_sync(0xffffffffu, sB, 1);
                sB += __shfl_xor_sync(0xffffffffu, sB, 2);
                float rA = 1.f / sA, rB = 1.f / sB;

                // AV: out = P V (1-term, P = unnormalized exp), V from hoisted frags
                float av[4][4];
                #pragma unroll
                for (int nd = 0; nd < 4; nd++)
                    #pragma unroll
                    for (int q = 0; q < 4; q++) av[nd][q] = 0.f;
                #pragma unroll
                for (int jt = 0; jt < 4; jt++) {
                    int nA = 2 * jt, nB = 2 * jt + 1;
                    uint32_t ph[4];
                    ph[0] = hpack(sc[nA][0], sc[nA][1]);
                    ph[1] = hpack(sc[nA][2], sc[nA][3]);
                    if (nB < 7) {
                        ph[2] = hpack(sc[nB][0], sc[nB][1]);
                        ph[3] = hpack(sc[nB][2], sc[nB][3]);
                    } else { ph[2] = 0; ph[3] = 0; }
                    #pragma unroll
                    for (int nd = 0; nd < 4; nd++) {
                        int p = nd >> 1, q = nd & 1;
                        uint2 BH = make_uint2(vf[jt * 8 + p * 4 + 2 * q],
                                              vf[jt * 8 + p * 4 + 2 * q + 1]);
                        mma16816(av[nd], ph, BH);
                    }
                }

                // normalize in fp32, store AV out (single fp16) as proj A input
                #pragma unroll
                for (int nd = 0; nd < 4; nd++) {
                    int col = qo + nd * 8 + tig * 2;
                    if (i0 < NTOK)
                        *(uint32_t*)(xhi + (wo + i0) * ST + col) =
                            hpack(av[nd][0] * rA, av[nd][1] * rA);
                    if (i1 < NTOK)
                        *(uint32_t*)(xhi + (wo + i1) * ST + col) =
                            hpack(av[nd][2] * rB, av[nd][3] * rB);
                }
            }
        }
    }

    // preload proj fragments BEFORE the barrier (sc/av dead; LDG spans the barrier)
    load_frags<2>(g_bproj + (size_t)(warp * 2) * 384 + lane, pre);
    __syncthreads();

    // ---------------- Phase 4: proj GEMM (1-term), M=112, 24 n-tiles / 12 warps ----------------
    {
        const int ntbase = warp * 2;
        float acc[2][7][4];
        gemm_chunk7_pre<2>(aHi, pre, acc);
        #pragma unroll
        for (int n = 0; n < 2; n++) {
            int col = (ntbase + n) * 8 + tig * 2;
            float b0 = proj_b[col], b1 = proj_b[col + 1];
            #pragma unroll
            for (int m = 0; m < 7; m++) {
                int r0 = m * 16 + gid;
                int r1 = r0 + 8;
                if (row_valid(r0)) {
                    int w = (r0 >= WOFF) ? 1 : 0;
                    float* og = out + ((size_t)(bw0 + w) * NTOK + (r0 - w * WOFF)) * DIM;
                    *(float2*)(og + col) = make_float2(acc[n][m][0] + b0, acc[n][m][1] + b1);
                }
                if (row_valid(r1)) {
                    int w = (r1 >= WOFF) ? 1 : 0;
                    float* og = out + ((size_t)(bw0 + w) * NTOK + (r1 - w * WOFF)) * DIM;
                    *(float2*)(og + col) = make_float2(acc[n][m][2] + b0, acc[n][m][3] + b1);
                }
            }
        }
    }
}

extern "C" void kernel_launch(void* const* d_in, const int* in_sizes, int n_in,
                              void* d_out, int out_size)
{
    const float* x      = (const float*)d_in[0];
    const int*   rpi    = (const int*)d_in[1];
    const float* mask   = (const float*)d_in[2];
    const float* qkv_w  = (const float*)d_in[3];
    const float* qkv_b  = (const float*)d_in[4];
    const float* proj_w = (const float*)d_in[5];
    const float* proj_b = (const float*)d_in[6];
    const float* rpb    = (const float*)d_in[7];

    prep_all<<<(NQF + NPF + CM_N + 255) / 256, 256>>>(qkv_w, proj_w, rpi, mask, rpb);

    cudaFuncSetAttribute(win_attn_kernel,
                         cudaFuncAttributeMaxDynamicSharedMemorySize, SM_TOTAL);
    win_attn_kernel<<<2048, THREADS, SM_TOTAL>>>(x, qkv_b, proj_b, (float*)d_out);
}